// round 1
// baseline (speedup 1.0000x reference)
#include <cuda_runtime.h>
#include <math.h>

// ---------------- problem constants ----------------
#define CN0 100000
#define CN1 20000
#define CN2 4000
#define CR 3
#define CE0 160000
#define CE1 64000
#define CHID 128
#define CFEAT 256

// ---------------- device scratch (no cudaMalloc allowed) ----------------
__device__ __align__(16) float g_feat0[CN0 * CFEAT];     // 102.4 MB
__device__ __align__(16) float g_feat1[CN1 * CFEAT];     // 20.5 MB
__device__ __align__(16) float g_msg[CN1 * 768];         // 61.4 MB (reused layer2)
__device__ __align__(16) float g_H[CN1 * 256];           // 20.5 MB (fc1/fc2 concat + attn scratch)
__device__ __align__(16) float g_z[CR * CN1 * CHID];     // 30.7 MB (reused layer2)
__device__ int   g_cnt[CN1];
__device__ int   g_rowptr[CN1 + 1];
__device__ int   g_cursor[CN1 + 1];
__device__ int   g_sorted[CE0];
__device__ float g_s[CR];
__device__ float g_beta[CR];

// ---------------- tiny utility kernels ----------------
__global__ void zeroi_k(int* p, int n) {
    int i = blockIdx.x * blockDim.x + threadIdx.x;
    if (i < n) p[i] = 0;
}
__global__ void zerof_k(float* p, int n) {
    int i = blockIdx.x * blockDim.x + threadIdx.x;
    if (i < n) p[i] = 0.f;
}

// ---------------- CSR build ----------------
__global__ void hist_k(const int* __restrict__ dst, int E, int* cnt) {
    int e = blockIdx.x * blockDim.x + threadIdx.x;
    if (e < E) atomicAdd(&cnt[dst[e]], 1);
}

// single-block exclusive scan (n up to ~20000)
__global__ void scan_k(const int* __restrict__ cnt, int* rowptr, int* cursor, int n) {
    __shared__ int sh[1024];
    __shared__ int carry_s;
    if (threadIdx.x == 0) carry_s = 0;
    __syncthreads();
    for (int base = 0; base < n; base += 1024) {
        int i = base + threadIdx.x;
        int v = (i < n) ? cnt[i] : 0;
        sh[threadIdx.x] = v;
        __syncthreads();
        for (int off = 1; off < 1024; off <<= 1) {
            int add = (threadIdx.x >= off) ? sh[threadIdx.x - off] : 0;
            __syncthreads();
            sh[threadIdx.x] += add;
            __syncthreads();
        }
        int carry = carry_s;
        if (i < n) {
            int excl = carry + sh[threadIdx.x] - v;
            rowptr[i] = excl;
            cursor[i] = excl;
        }
        __syncthreads();
        if (threadIdx.x == 0) carry_s = carry + sh[1023];
        __syncthreads();
    }
    if (threadIdx.x == 0) rowptr[n] = carry_s;
}

__global__ void scatter_k(const int* __restrict__ src, const int* __restrict__ dst,
                          int E, int* cursor, int* sorted) {
    int e = blockIdx.x * blockDim.x + threadIdx.x;
    if (e < E) {
        int p = atomicAdd(&cursor[dst[e]], 1);
        sorted[p] = src[e];
    }
}

// ---------------- segment aggregation (max | mean | sum) ----------------
// one block per destination node; 256 threads = 256 features; no atomics.
__global__ void aggregate_k(const float* __restrict__ feat,
                            const int* __restrict__ rowptr,
                            const int* __restrict__ sorted,
                            float* __restrict__ msg) {
    int n = blockIdx.x;
    int start = rowptr[n], end = rowptr[n + 1];
    int deg = end - start;
    int f = threadIdx.x;
    float sum = 0.f, mx = -3.402823e38f;
    __shared__ int eids[256];
    for (int base = start; base < end; base += 256) {
        int cnt = min(256, end - base);
        __syncthreads();
        if (threadIdx.x < cnt) eids[threadIdx.x] = sorted[base + threadIdx.x];
        __syncthreads();
        for (int i = 0; i < cnt; i++) {
            float v = feat[(size_t)eids[i] * CFEAT + f];
            sum += v;
            mx = fmaxf(mx, v);
        }
    }
    if (deg == 0) mx = 0.f;
    float mean = sum / (float)max(deg, 1);
    size_t o = (size_t)n * 768 + f;
    msg[o]       = mx;
    msg[o + 256] = mean;
    msg[o + 512] = sum;
}

// ---------------- generic fp32 GEMM: C[M,128] = A[M,K] @ W[K,128] + b ----------------
// BM=BN=128, BK=8, 256 threads, 8x8 microtile per thread.
__global__ void __launch_bounds__(256, 2)
gemm_k(const float* __restrict__ A, int lda,
       const float* __restrict__ W, const float* __restrict__ bias,
       float* __restrict__ C, int ldc, int M, int K, int do_relu) {
    __shared__ float As[8][128];
    __shared__ float Ws[8][128];
    int m0 = blockIdx.x * 128;
    int t = threadIdx.x;
    int arow = t >> 1, akoff = (t & 1) * 4;
    int wk = t >> 5, wn = (t & 31) * 4;
    int tx = t & 15, ty = t >> 4;
    float acc[8][8];
#pragma unroll
    for (int i = 0; i < 8; i++)
#pragma unroll
        for (int j = 0; j < 8; j++) acc[i][j] = 0.f;

    for (int kb = 0; kb < K; kb += 8) {
        int gm = m0 + arow;
        float4 av = make_float4(0.f, 0.f, 0.f, 0.f);
        if (gm < M) av = *reinterpret_cast<const float4*>(A + (size_t)gm * lda + kb + akoff);
        As[akoff + 0][arow] = av.x;
        As[akoff + 1][arow] = av.y;
        As[akoff + 2][arow] = av.z;
        As[akoff + 3][arow] = av.w;
        float4 wv = *reinterpret_cast<const float4*>(W + (size_t)(kb + wk) * 128 + wn);
        *reinterpret_cast<float4*>(&Ws[wk][wn]) = wv;
        __syncthreads();
#pragma unroll
        for (int k = 0; k < 8; k++) {
            float a[8], b[8];
            *(float4*)(a)     = *(float4*)&As[k][ty * 8];
            *(float4*)(a + 4) = *(float4*)&As[k][ty * 8 + 4];
            *(float4*)(b)     = *(float4*)&Ws[k][tx * 8];
            *(float4*)(b + 4) = *(float4*)&Ws[k][tx * 8 + 4];
#pragma unroll
            for (int i = 0; i < 8; i++)
#pragma unroll
                for (int j = 0; j < 8; j++)
                    acc[i][j] = fmaf(a[i], b[j], acc[i][j]);
        }
        __syncthreads();
    }
#pragma unroll
    for (int i = 0; i < 8; i++) {
        int gm = m0 + ty * 8 + i;
        if (gm >= M) continue;
#pragma unroll
        for (int j = 0; j < 8; j += 4) {
            int c = tx * 8 + j;
            float4 v;
            v.x = acc[i][j + 0] + bias[c + 0];
            v.y = acc[i][j + 1] + bias[c + 1];
            v.z = acc[i][j + 2] + bias[c + 2];
            v.w = acc[i][j + 3] + bias[c + 3];
            if (do_relu) {
                v.x = fmaxf(v.x, 0.f); v.y = fmaxf(v.y, 0.f);
                v.z = fmaxf(v.z, 0.f); v.w = fmaxf(v.w, 0.f);
            }
            *reinterpret_cast<float4*>(C + (size_t)gm * ldc + c) = v;
        }
    }
}

// ---------------- feature assembly ----------------
// fill feat0 columns 128..255 with tss/rs embeddings
__global__ void fill_embed_k(const float* __restrict__ tss, const float* __restrict__ rs,
                             const int* __restrict__ nid, float* __restrict__ feat) {
    int n = blockIdx.x;
    int c = threadIdx.x;  // 0..127
    int id = nid[n];
    float v = (c < 64) ? tss[(size_t)id * 64 + c] : rs[(size_t)id * 64 + (c - 64)];
    feat[(size_t)n * CFEAT + 128 + c] = v;
}

// h1 = relu(sum_r beta_r z_r) fused with tss/rs concat -> feat1
__global__ void combine1_k(const float* __restrict__ z, const float* __restrict__ beta,
                           const float* __restrict__ tss, const float* __restrict__ rs,
                           const int* __restrict__ nid, float* __restrict__ feat1, int N) {
    int n = blockIdx.x;
    int c = threadIdx.x;  // 0..255
    if (c < 128) {
        float v = beta[0] * z[(size_t)n * 128 + c]
                + beta[1] * z[(size_t)N * 128 + (size_t)n * 128 + c]
                + beta[2] * z[2 * (size_t)N * 128 + (size_t)n * 128 + c];
        feat1[(size_t)n * CFEAT + c] = fmaxf(v, 0.f);
    } else if (c < 192) {
        feat1[(size_t)n * CFEAT + c] = tss[(size_t)nid[n] * 64 + (c - 128)];
    } else {
        feat1[(size_t)n * CFEAT + c] = rs[(size_t)nid[n] * 64 + (c - 192)];
    }
}

// ---------------- semantic attention ----------------
// t = [N,128] (already z@w1+b1); accumulate sum_n sum_c tanh(t)*w2 into sdst
__global__ void attn_reduce_k(const float* __restrict__ t, const float* __restrict__ w2,
                              float* sdst, int N) {
    int n = blockIdx.x * 8 + (threadIdx.x >> 5);
    int lane = threadIdx.x & 31;
    float part = 0.f;
    if (n < N) {
#pragma unroll
        for (int j = 0; j < 4; j++) {
            int c = lane + 32 * j;
            part += tanhf(t[(size_t)n * 128 + c]) * w2[c];
        }
    }
    for (int o = 16; o; o >>= 1) part += __shfl_xor_sync(0xffffffffu, part, o);
    __shared__ float bs[8];
    if (lane == 0) bs[threadIdx.x >> 5] = part;
    __syncthreads();
    if (threadIdx.x == 0) {
        float tot = 0.f;
        for (int i = 0; i < 8; i++) tot += bs[i];
        atomicAdd(sdst, tot);
    }
}

__global__ void beta_k(const float* __restrict__ s, float* beta, float invN) {
    if (threadIdx.x == 0) {
        float w0 = s[0] * invN, w1 = s[1] * invN, w2 = s[2] * invN;
        float m = fmaxf(w0, fmaxf(w1, w2));
        float e0 = expf(w0 - m), e1 = expf(w1 - m), e2 = expf(w2 - m);
        float d = e0 + e1 + e2;
        beta[0] = e0 / d; beta[1] = e1 / d; beta[2] = e2 / d;
    }
}

// ---------------- final head: sigmoid((sum_r beta_r z2_r) @ pred_w + b) ----------------
__global__ void final_k(const float* __restrict__ z, const float* __restrict__ beta,
                        const float* __restrict__ pred_w, const float* __restrict__ pred_b,
                        float* __restrict__ out, int N) {
    int n = blockIdx.x * 8 + (threadIdx.x >> 5);
    int lane = threadIdx.x & 31;
    if (n >= N) return;
    float acc = 0.f;
#pragma unroll
    for (int j = 0; j < 4; j++) {
        int c = lane + 32 * j;
        float h = beta[0] * z[(size_t)n * 128 + c]
                + beta[1] * z[(size_t)N * 128 + (size_t)n * 128 + c]
                + beta[2] * z[2 * (size_t)N * 128 + (size_t)n * 128 + c];
        acc += h * pred_w[c];
    }
    for (int o = 16; o; o >>= 1) acc += __shfl_xor_sync(0xffffffffu, acc, o);
    if (lane == 0) out[n] = 1.f / (1.f + expf(-(acc + pred_b[0])));
}

// ---------------- host orchestration ----------------
extern "C" void kernel_launch(void* const* d_in, const int* in_sizes, int n_in,
                              void* d_out, int out_size) {
    const float* x_user   = (const float*)d_in[0];
    const float* tss      = (const float*)d_in[1];
    const float* rs       = (const float*)d_in[2];
    const int*   src_nid0 = (const int*)d_in[3];
    const int*   src_nid1 = (const int*)d_in[4];
    const int*   e0_src   = (const int*)d_in[5];
    const int*   e0_dst   = (const int*)d_in[6];
    const int*   e1_src   = (const int*)d_in[7];
    const int*   e1_dst   = (const int*)d_in[8];
    const float* embed_w  = (const float*)d_in[9];
    const float* embed_b  = (const float*)d_in[10];
    const float* l1_fc1_w = (const float*)d_in[11];
    const float* l1_fc1_b = (const float*)d_in[12];
    const float* l1_fc2_w = (const float*)d_in[13];
    const float* l1_fc2_b = (const float*)d_in[14];
    const float* l1_fc3_w = (const float*)d_in[15];
    const float* l1_fc3_b = (const float*)d_in[16];
    const float* l2_fc1_w = (const float*)d_in[17];
    const float* l2_fc1_b = (const float*)d_in[18];
    const float* l2_fc2_w = (const float*)d_in[19];
    const float* l2_fc2_b = (const float*)d_in[20];
    const float* l2_fc3_w = (const float*)d_in[21];
    const float* l2_fc3_b = (const float*)d_in[22];
    const float* attn_w1  = (const float*)d_in[23];
    const float* attn_b1  = (const float*)d_in[24];
    const float* attn_w2  = (const float*)d_in[25];
    const float* pred_w   = (const float*)d_in[26];
    const float* pred_b   = (const float*)d_in[27];
    float* out = (float*)d_out;

    float *feat0, *feat1, *msg, *H, *z, *s, *beta;
    int *cnt, *rowptr, *cursor, *sorted;
    cudaGetSymbolAddress((void**)&feat0, g_feat0);
    cudaGetSymbolAddress((void**)&feat1, g_feat1);
    cudaGetSymbolAddress((void**)&msg, g_msg);
    cudaGetSymbolAddress((void**)&H, g_H);
    cudaGetSymbolAddress((void**)&z, g_z);
    cudaGetSymbolAddress((void**)&s, g_s);
    cudaGetSymbolAddress((void**)&beta, g_beta);
    cudaGetSymbolAddress((void**)&cnt, g_cnt);
    cudaGetSymbolAddress((void**)&rowptr, g_rowptr);
    cudaGetSymbolAddress((void**)&cursor, g_cursor);
    cudaGetSymbolAddress((void**)&sorted, g_sorted);

    // feat0 = [x_user@embed_w + b | tss[nid0] | rs[nid0]]
    gemm_k<<<(CN0 + 127) / 128, 256>>>(x_user, 128, embed_w, embed_b, feat0, CFEAT, CN0, 128, 0);
    fill_embed_k<<<CN0, 128>>>(tss, rs, src_nid0, feat0);

    // ---- layer 1 convs ----
    for (int r = 0; r < CR; r++) {
        const int* es = e0_src + r * CE0;
        const int* ed = e0_dst + r * CE0;
        zeroi_k<<<(CN1 + 255) / 256, 256>>>(cnt, CN1);
        hist_k<<<(CE0 + 255) / 256, 256>>>(ed, CE0, cnt);
        scan_k<<<1, 1024>>>(cnt, rowptr, cursor, CN1);
        scatter_k<<<(CE0 + 255) / 256, 256>>>(es, ed, CE0, cursor, sorted);
        aggregate_k<<<CN1, 256>>>(feat0, rowptr, sorted, msg);
        gemm_k<<<(CN1 + 127) / 128, 256>>>(msg, 768, l1_fc2_w + (size_t)r * 768 * 128,
                                           l1_fc2_b + r * 128, H, 256, CN1, 768, 1);
        gemm_k<<<(CN1 + 127) / 128, 256>>>(feat0, 256, l1_fc1_w + (size_t)r * 256 * 128,
                                           l1_fc1_b + r * 128, H + 128, 256, CN1, 256, 1);
        gemm_k<<<(CN1 + 127) / 128, 256>>>(H, 256, l1_fc3_w + (size_t)r * 256 * 128,
                                           l1_fc3_b + r * 128, z + (size_t)r * CN1 * 128, 128, CN1, 256, 0);
    }

    // ---- attention 1 -> feat1 ----
    zerof_k<<<1, 32>>>(s, CR);
    for (int r = 0; r < CR; r++) {
        gemm_k<<<(CN1 + 127) / 128, 256>>>(z + (size_t)r * CN1 * 128, 128, attn_w1, attn_b1,
                                           H, 128, CN1, 128, 0);
        attn_reduce_k<<<(CN1 + 7) / 8, 256>>>(H, attn_w2, s + r, CN1);
    }
    beta_k<<<1, 32>>>(s, beta, 1.0f / (float)CN1);
    combine1_k<<<CN1, 256>>>(z, beta, tss, rs, src_nid1, feat1, CN1);

    // ---- layer 2 convs ----
    for (int r = 0; r < CR; r++) {
        const int* es = e1_src + r * CE1;
        const int* ed = e1_dst + r * CE1;
        zeroi_k<<<(CN2 + 255) / 256, 256>>>(cnt, CN2);
        hist_k<<<(CE1 + 255) / 256, 256>>>(ed, CE1, cnt);
        scan_k<<<1, 1024>>>(cnt, rowptr, cursor, CN2);
        scatter_k<<<(CE1 + 255) / 256, 256>>>(es, ed, CE1, cursor, sorted);
        aggregate_k<<<CN2, 256>>>(feat1, rowptr, sorted, msg);
        gemm_k<<<(CN2 + 127) / 128, 256>>>(msg, 768, l2_fc2_w + (size_t)r * 768 * 128,
                                           l2_fc2_b + r * 128, H, 256, CN2, 768, 1);
        gemm_k<<<(CN2 + 127) / 128, 256>>>(feat1, 256, l2_fc1_w + (size_t)r * 256 * 128,
                                           l2_fc1_b + r * 128, H + 128, 256, CN2, 256, 1);
        gemm_k<<<(CN2 + 127) / 128, 256>>>(H, 256, l2_fc3_w + (size_t)r * 256 * 128,
                                           l2_fc3_b + r * 128, z + (size_t)r * CN2 * 128, 128, CN2, 256, 0);
    }

    // ---- attention 2 + prediction ----
    zerof_k<<<1, 32>>>(s, CR);
    for (int r = 0; r < CR; r++) {
        gemm_k<<<(CN2 + 127) / 128, 256>>>(z + (size_t)r * CN2 * 128, 128, attn_w1, attn_b1,
                                           H, 128, CN2, 128, 0);
        attn_reduce_k<<<(CN2 + 7) / 8, 256>>>(H, attn_w2, s + r, CN2);
    }
    beta_k<<<1, 32>>>(s, beta, 1.0f / (float)CN2);
    final_k<<<(CN2 + 7) / 8, 256>>>(z, beta, pred_w, pred_b, out, CN2);
}

// round 4
// speedup vs baseline: 1.8169x; 1.8169x over previous
#include <cuda_runtime.h>
#include <cuda_bf16.h>
#include <math.h>
#include <stdint.h>

// ---------------- problem constants ----------------
#define CN0 100000
#define CN1 20000
#define CN2 4000
#define CR 3
#define CE0 160000
#define CE1 64000
#define CHID 128
#define CFEAT 256

// weight-transpose buffer offsets (elements)
#define OFF_EMBED 0
#define OFF_ATTN  16384
#define OFF_L1FC1 32768
#define OFF_L1FC2 131072
#define OFF_L1FC3 425984
#define OFF_L2FC1 524288
#define OFF_L2FC2 622592
#define OFF_L2FC3 917504
#define WT_TOTAL  1015808

// ---------------- device scratch ----------------
__device__ __align__(16) float g_feat0[CN0 * CFEAT];
__device__ __align__(16) float g_feat1[CN1 * CFEAT];
__device__ __align__(16) float g_z[CR * CN1 * CHID];
__device__ __align__(16) float g_t[CN1 * CHID];
__device__ __align__(16) __nv_bfloat16 g_xh[CN0 * 128];
__device__ __align__(16) __nv_bfloat16 g_xl[CN0 * 128];
__device__ __align__(16) __nv_bfloat16 g_f0h[CN1 * CFEAT];
__device__ __align__(16) __nv_bfloat16 g_f0l[CN1 * CFEAT];
__device__ __align__(16) __nv_bfloat16 g_f1h[CN1 * CFEAT];
__device__ __align__(16) __nv_bfloat16 g_f1l[CN1 * CFEAT];
__device__ __align__(16) __nv_bfloat16 g_msgh[CN1 * 768];
__device__ __align__(16) __nv_bfloat16 g_msgl[CN1 * 768];
__device__ __align__(16) __nv_bfloat16 g_Hh[CN1 * 256];
__device__ __align__(16) __nv_bfloat16 g_Hl[CN1 * 256];
__device__ __align__(16) __nv_bfloat16 g_zh[CR * CN1 * CHID];
__device__ __align__(16) __nv_bfloat16 g_zl[CR * CN1 * CHID];
__device__ __align__(16) __nv_bfloat16 g_wth[WT_TOTAL];
__device__ __align__(16) __nv_bfloat16 g_wtl[WT_TOTAL];
__device__ int   g_cnt[CN1];
__device__ int   g_rowptr[CN1 + 1];
__device__ int   g_cursor[CN1 + 1];
__device__ int   g_sorted[CE0];
__device__ float g_s[CR];
__device__ float g_beta[CR];

// ---------------- helpers ----------------
__device__ __forceinline__ uint32_t smem_u32(const void* p) {
    uint32_t a;
    asm("{ .reg .u64 t; cvta.to.shared.u64 t, %1; cvt.u32.u64 %0, t; }" : "=r"(a) : "l"(p));
    return a;
}
__device__ __forceinline__ void bsplit(float v, __nv_bfloat16& h, __nv_bfloat16& l) {
    h = __float2bfloat16(v);
    l = __float2bfloat16(v - __bfloat162float(h));
}
__device__ __forceinline__ void cp16(uint32_t dst, const void* src, int valid) {
    asm volatile("cp.async.cg.shared.global [%0], [%1], 16, %2;"
                 :: "r"(dst), "l"(src), "r"(valid ? 16 : 0) : "memory");
}
template <int N> __device__ __forceinline__ void cpwait() {
    asm volatile("cp.async.wait_group %0;" :: "n"(N) : "memory");
}
__device__ __forceinline__ void cpcommit() {
    asm volatile("cp.async.commit_group;" ::: "memory");
}
__device__ __forceinline__ void mma16816(float* c, const uint32_t* a, uint32_t b0, uint32_t b1) {
    asm volatile("mma.sync.aligned.m16n8k16.row.col.f32.bf16.bf16.f32 "
        "{%0,%1,%2,%3}, {%4,%5,%6,%7}, {%8,%9}, {%0,%1,%2,%3};"
        : "+f"(c[0]), "+f"(c[1]), "+f"(c[2]), "+f"(c[3])
        : "r"(a[0]), "r"(a[1]), "r"(a[2]), "r"(a[3]), "r"(b0), "r"(b1));
}

// ---------------- tensor-core GEMM (mma.sync, bf16 3-term split) ----------------
// C[M,128] = (Ah+Al)[M,K] @ (Bth+Btl)^T + bias ; Bt is [128,K] pre-transposed.
#define KC 32
#define SROW 40                       // padded smem row stride (elements)
#define MAT_BYTES (128 * SROW * 2)    // 10240
#define STAGE_BYTES (4 * MAT_BYTES)   // 40960
#define GEMM_SMEM_BYTES (2 * STAGE_BYTES)  // 81920

__global__ void __launch_bounds__(256)
gemm_tc(const __nv_bfloat16* __restrict__ Ah, const __nv_bfloat16* __restrict__ Al,
        const __nv_bfloat16* __restrict__ Bth, const __nv_bfloat16* __restrict__ Btl,
        const float* __restrict__ bias,
        float* __restrict__ Cf, __nv_bfloat16* __restrict__ Ch, __nv_bfloat16* __restrict__ Cl,
        int ldc, int M, int K, int relu) {
    extern __shared__ __align__(16) char sm[];
    __shared__ float bias_s[128];
    uint32_t sb = smem_u32(sm);
    int t = threadIdx.x;
    int lane = t & 31, wid = t >> 5;
    int m0 = blockIdx.x * 128;
    if (t < 128) bias_s[t] = bias[t];

    float acc[2][8][4];
#pragma unroll
    for (int i = 0; i < 2; i++)
#pragma unroll
        for (int j = 0; j < 8; j++)
#pragma unroll
            for (int q = 0; q < 4; q++) acc[i][j][q] = 0.f;

    const int nC = K >> 5;
    const int wm = (wid >> 1) * 32, wn = (wid & 1) * 64;
    const int t4 = lane >> 2, q2 = (lane & 3) * 2;

    auto load_stage = [&](int st, int c) {
        uint32_t base = sb + st * STAGE_BYTES;
        int kb = c * KC;
#pragma unroll
        for (int h = 0; h < 2; h++) {
            int chunk = t + h * 256;          // 0..511
            int row = chunk >> 2, seg = chunk & 3;
            uint32_t off = (uint32_t)(row * (SROW * 2) + seg * 16);
            int gk = kb + seg * 8;
            int av = (m0 + row) < M;
            size_t arow = (size_t)(av ? (m0 + row) : 0) * K + gk;
            cp16(base + off,                 Ah + arow, av);
            cp16(base + MAT_BYTES + off,     Al + arow, av);
            size_t brow = (size_t)row * K + gk;
            cp16(base + 2 * MAT_BYTES + off, Bth + brow, 1);
            cp16(base + 3 * MAT_BYTES + off, Btl + brow, 1);
        }
        cpcommit();
    };

    auto compute_stage = [&](int st) {
        const char* base = sm + st * STAGE_BYTES;
        const __nv_bfloat16* sAh = (const __nv_bfloat16*)base;
        const __nv_bfloat16* sAl = (const __nv_bfloat16*)(base + MAT_BYTES);
        const __nv_bfloat16* sBh = (const __nv_bfloat16*)(base + 2 * MAT_BYTES);
        const __nv_bfloat16* sBl = (const __nv_bfloat16*)(base + 3 * MAT_BYTES);
#pragma unroll
        for (int k16 = 0; k16 < 2; k16++) {
            int k0 = k16 * 16;
            uint32_t ah[2][4], al[2][4];
#pragma unroll
            for (int i = 0; i < 2; i++) {
                int r = wm + i * 16 + t4;
                ah[i][0] = *(const uint32_t*)&sAh[r * SROW + k0 + q2];
                ah[i][1] = *(const uint32_t*)&sAh[(r + 8) * SROW + k0 + q2];
                ah[i][2] = *(const uint32_t*)&sAh[r * SROW + k0 + q2 + 8];
                ah[i][3] = *(const uint32_t*)&sAh[(r + 8) * SROW + k0 + q2 + 8];
                al[i][0] = *(const uint32_t*)&sAl[r * SROW + k0 + q2];
                al[i][1] = *(const uint32_t*)&sAl[(r + 8) * SROW + k0 + q2];
                al[i][2] = *(const uint32_t*)&sAl[r * SROW + k0 + q2 + 8];
                al[i][3] = *(const uint32_t*)&sAl[(r + 8) * SROW + k0 + q2 + 8];
            }
#pragma unroll
            for (int j = 0; j < 8; j++) {
                int bn = wn + j * 8 + t4;
                uint32_t bh0 = *(const uint32_t*)&sBh[bn * SROW + k0 + q2];
                uint32_t bh1 = *(const uint32_t*)&sBh[bn * SROW + k0 + q2 + 8];
                uint32_t bl0 = *(const uint32_t*)&sBl[bn * SROW + k0 + q2];
                uint32_t bl1 = *(const uint32_t*)&sBl[bn * SROW + k0 + q2 + 8];
#pragma unroll
                for (int i = 0; i < 2; i++) {
                    mma16816(acc[i][j], ah[i], bh0, bh1);
                    mma16816(acc[i][j], ah[i], bl0, bl1);
                    mma16816(acc[i][j], al[i], bh0, bh1);
                }
            }
        }
    };

    load_stage(0, 0);
    for (int c = 0; c < nC; c++) {
        if (c + 1 < nC) {
            load_stage((c + 1) & 1, c + 1);
            cpwait<1>();
        } else {
            cpwait<0>();
        }
        __syncthreads();
        compute_stage(c & 1);
        __syncthreads();
    }

    // epilogue: bias + relu, write fp32 and/or bf16 split
#pragma unroll
    for (int i = 0; i < 2; i++) {
        int r0 = m0 + wm + i * 16 + t4;
#pragma unroll
        for (int j = 0; j < 8; j++) {
            int col = wn + j * 8 + q2;
            float b0v = bias_s[col], b1v = bias_s[col + 1];
            float v00 = acc[i][j][0] + b0v, v01 = acc[i][j][1] + b1v;
            float v10 = acc[i][j][2] + b0v, v11 = acc[i][j][3] + b1v;
            if (relu) {
                v00 = fmaxf(v00, 0.f); v01 = fmaxf(v01, 0.f);
                v10 = fmaxf(v10, 0.f); v11 = fmaxf(v11, 0.f);
            }
            if (r0 < M) {
                if (Cf) *(float2*)(Cf + (size_t)r0 * ldc + col) = make_float2(v00, v01);
                if (Ch) {
                    __nv_bfloat16 h0, l0, h1, l1;
                    bsplit(v00, h0, l0); bsplit(v01, h1, l1);
                    __nv_bfloat162 hh; hh.x = h0; hh.y = h1;
                    __nv_bfloat162 ll; ll.x = l0; ll.y = l1;
                    *(__nv_bfloat162*)(Ch + (size_t)r0 * ldc + col) = hh;
                    *(__nv_bfloat162*)(Cl + (size_t)r0 * ldc + col) = ll;
                }
            }
            if (r0 + 8 < M) {
                if (Cf) *(float2*)(Cf + (size_t)(r0 + 8) * ldc + col) = make_float2(v10, v11);
                if (Ch) {
                    __nv_bfloat16 h0, l0, h1, l1;
                    bsplit(v10, h0, l0); bsplit(v11, h1, l1);
                    __nv_bfloat162 hh; hh.x = h0; hh.y = h1;
                    __nv_bfloat162 ll; ll.x = l0; ll.y = l1;
                    *(__nv_bfloat162*)(Ch + (size_t)(r0 + 8) * ldc + col) = hh;
                    *(__nv_bfloat162*)(Cl + (size_t)(r0 + 8) * ldc + col) = ll;
                }
            }
        }
    }
}

// ---------------- conversions ----------------
__global__ void split_k(const float* __restrict__ src, __nv_bfloat16* __restrict__ h,
                        __nv_bfloat16* __restrict__ l, long n) {
    long i = (long)blockIdx.x * blockDim.x + threadIdx.x;
    if (i < n) {
        __nv_bfloat16 hh, ll;
        bsplit(src[i], hh, ll);
        h[i] = hh; l[i] = ll;
    }
}
// w: [R,K,128] -> th/tl: [R,128,K] (transposed per relation)
__global__ void wconv_k(const float* __restrict__ w, __nv_bfloat16* __restrict__ th,
                        __nv_bfloat16* __restrict__ tl, int K, int R) {
    long i = (long)blockIdx.x * blockDim.x + threadIdx.x;
    long tot = (long)R * K * 128;
    if (i >= tot) return;
    int r = (int)(i / ((long)K * 128));
    int rem = (int)(i % ((long)K * 128));
    int k = rem >> 7, n = rem & 127;
    __nv_bfloat16 hh, ll;
    bsplit(w[i], hh, ll);
    size_t o = (size_t)r * K * 128 + (size_t)n * K + k;
    th[o] = hh; tl[o] = ll;
}

// ---------------- CSR build ----------------
__global__ void zeroi_k(int* p, int n) {
    int i = blockIdx.x * blockDim.x + threadIdx.x;
    if (i < n) p[i] = 0;
}
__global__ void zerof_k(float* p, int n) {
    int i = blockIdx.x * blockDim.x + threadIdx.x;
    if (i < n) p[i] = 0.f;
}
__global__ void hist_k(const int* __restrict__ dst, int E, int* cnt) {
    int e = blockIdx.x * blockDim.x + threadIdx.x;
    if (e < E) atomicAdd(&cnt[dst[e]], 1);
}
__global__ void scan_k(const int* __restrict__ cnt, int* rowptr, int* cursor, int n) {
    __shared__ int sh[1024];
    __shared__ int carry_s;
    if (threadIdx.x == 0) carry_s = 0;
    __syncthreads();
    for (int base = 0; base < n; base += 1024) {
        int i = base + threadIdx.x;
        int v = (i < n) ? cnt[i] : 0;
        sh[threadIdx.x] = v;
        __syncthreads();
        for (int off = 1; off < 1024; off <<= 1) {
            int add = (threadIdx.x >= off) ? sh[threadIdx.x - off] : 0;
            __syncthreads();
            sh[threadIdx.x] += add;
            __syncthreads();
        }
        int carry = carry_s;
        if (i < n) {
            int excl = carry + sh[threadIdx.x] - v;
            rowptr[i] = excl;
            cursor[i] = excl;
        }
        __syncthreads();
        if (threadIdx.x == 0) carry_s = carry + sh[1023];
        __syncthreads();
    }
    if (threadIdx.x == 0) rowptr[n] = carry_s;
}
__global__ void scatter_k(const int* __restrict__ src, const int* __restrict__ dst,
                          int E, int* cursor, int* sorted) {
    int e = blockIdx.x * blockDim.x + threadIdx.x;
    if (e < E) {
        int p = atomicAdd(&cursor[dst[e]], 1);
        sorted[p] = src[e];
    }
}

// ---------------- segment aggregation -> bf16 split msg ----------------
__global__ void aggregate_k(const float* __restrict__ feat,
                            const int* __restrict__ rowptr,
                            const int* __restrict__ sorted,
                            __nv_bfloat16* __restrict__ mh,
                            __nv_bfloat16* __restrict__ ml) {
    int n = blockIdx.x;
    int start = rowptr[n], end = rowptr[n + 1];
    int deg = end - start;
    int f = threadIdx.x;
    float sum = 0.f, mx = -3.402823e38f;
    __shared__ int eids[256];
    for (int base = start; base < end; base += 256) {
        int cnt = min(256, end - base);
        __syncthreads();
        if (threadIdx.x < cnt) eids[threadIdx.x] = sorted[base + threadIdx.x];
        __syncthreads();
        for (int i = 0; i < cnt; i++) {
            float v = feat[(size_t)eids[i] * CFEAT + f];
            sum += v;
            mx = fmaxf(mx, v);
        }
    }
    if (deg == 0) mx = 0.f;
    float mean = sum / (float)max(deg, 1);
    size_t o = (size_t)n * 768 + f;
    __nv_bfloat16 h, l;
    bsplit(mx, h, l);   mh[o] = h;        ml[o] = l;
    bsplit(mean, h, l); mh[o + 256] = h;  ml[o + 256] = l;
    bsplit(sum, h, l);  mh[o + 512] = h;  ml[o + 512] = l;
}

// ---------------- feature assembly ----------------
__global__ void fill_embed_k(const float* __restrict__ tss, const float* __restrict__ rs,
                             const int* __restrict__ nid, float* __restrict__ feat) {
    int n = blockIdx.x;
    int c = threadIdx.x;
    int id = nid[n];
    float v = (c < 64) ? tss[(size_t)id * 64 + c] : rs[(size_t)id * 64 + (c - 64)];
    feat[(size_t)n * CFEAT + 128 + c] = v;
}
__global__ void combine1_k(const float* __restrict__ z, const float* __restrict__ beta,
                           const float* __restrict__ tss, const float* __restrict__ rs,
                           const int* __restrict__ nid, float* __restrict__ feat1,
                           __nv_bfloat16* __restrict__ f1h, __nv_bfloat16* __restrict__ f1l,
                           int N) {
    int n = blockIdx.x;
    int c = threadIdx.x;  // 0..255
    float v;
    if (c < 128) {
        v = beta[0] * z[(size_t)n * 128 + c]
          + beta[1] * z[(size_t)N * 128 + (size_t)n * 128 + c]
          + beta[2] * z[2 * (size_t)N * 128 + (size_t)n * 128 + c];
        v = fmaxf(v, 0.f);
    } else if (c < 192) {
        v = tss[(size_t)nid[n] * 64 + (c - 128)];
    } else {
        v = rs[(size_t)nid[n] * 64 + (c - 192)];
    }
    size_t o = (size_t)n * CFEAT + c;
    feat1[o] = v;
    __nv_bfloat16 h, l;
    bsplit(v, h, l);
    f1h[o] = h; f1l[o] = l;
}

// ---------------- semantic attention ----------------
__global__ void attn_reduce_k(const float* __restrict__ t, const float* __restrict__ w2,
                              float* sdst, int N) {
    int n = blockIdx.x * 8 + (threadIdx.x >> 5);
    int lane = threadIdx.x & 31;
    float part = 0.f;
    if (n < N) {
#pragma unroll
        for (int j = 0; j < 4; j++) {
            int c = lane + 32 * j;
            part += tanhf(t[(size_t)n * 128 + c]) * w2[c];
        }
    }
    for (int o = 16; o; o >>= 1) part += __shfl_xor_sync(0xffffffffu, part, o);
    __shared__ float bs[8];
    if (lane == 0) bs[threadIdx.x >> 5] = part;
    __syncthreads();
    if (threadIdx.x == 0) {
        float tot = 0.f;
        for (int i = 0; i < 8; i++) tot += bs[i];
        atomicAdd(sdst, tot);
    }
}
__global__ void beta_k(const float* __restrict__ s, float* beta, float invN) {
    if (threadIdx.x == 0) {
        float w0 = s[0] * invN, w1 = s[1] * invN, w2 = s[2] * invN;
        float m = fmaxf(w0, fmaxf(w1, w2));
        float e0 = expf(w0 - m), e1 = expf(w1 - m), e2 = expf(w2 - m);
        float d = e0 + e1 + e2;
        beta[0] = e0 / d; beta[1] = e1 / d; beta[2] = e2 / d;
    }
}
__global__ void final_k(const float* __restrict__ z, const float* __restrict__ beta,
                        const float* __restrict__ pred_w, const float* __restrict__ pred_b,
                        float* __restrict__ out, int N) {
    int n = blockIdx.x * 8 + (threadIdx.x >> 5);
    int lane = threadIdx.x & 31;
    if (n >= N) return;
    float acc = 0.f;
#pragma unroll
    for (int j = 0; j < 4; j++) {
        int c = lane + 32 * j;
        float h = beta[0] * z[(size_t)n * 128 + c]
                + beta[1] * z[(size_t)N * 128 + (size_t)n * 128 + c]
                + beta[2] * z[2 * (size_t)N * 128 + (size_t)n * 128 + c];
        acc += h * pred_w[c];
    }
    for (int o = 16; o; o >>= 1) acc += __shfl_xor_sync(0xffffffffu, acc, o);
    if (lane == 0) out[n] = 1.f / (1.f + expf(-(acc + pred_b[0])));
}

// ---------------- host orchestration ----------------
static inline void launch_gemm(const __nv_bfloat16* Ah, const __nv_bfloat16* Al,
                               const __nv_bfloat16* Bth, const __nv_bfloat16* Btl,
                               const float* bias, float* Cf, __nv_bfloat16* Ch,
                               __nv_bfloat16* Cl, int ldc, int M, int K, int relu) {
    gemm_tc<<<(M + 127) / 128, 256, GEMM_SMEM_BYTES>>>(Ah, Al, Bth, Btl, bias, Cf, Ch, Cl,
                                                       ldc, M, K, relu);
}

extern "C" void kernel_launch(void* const* d_in, const int* in_sizes, int n_in,
                              void* d_out, int out_size) {
    const float* x_user   = (const float*)d_in[0];
    const float* tss      = (const float*)d_in[1];
    const float* rs       = (const float*)d_in[2];
    const int*   src_nid0 = (const int*)d_in[3];
    const int*   src_nid1 = (const int*)d_in[4];
    const int*   e0_src   = (const int*)d_in[5];
    const int*   e0_dst   = (const int*)d_in[6];
    const int*   e1_src   = (const int*)d_in[7];
    const int*   e1_dst   = (const int*)d_in[8];
    const float* embed_w  = (const float*)d_in[9];
    const float* embed_b  = (const float*)d_in[10];
    const float* l1_fc1_w = (const float*)d_in[11];
    const float* l1_fc1_b = (const float*)d_in[12];
    const float* l1_fc2_w = (const float*)d_in[13];
    const float* l1_fc2_b = (const float*)d_in[14];
    const float* l1_fc3_w = (const float*)d_in[15];
    const float* l1_fc3_b = (const float*)d_in[16];
    const float* l2_fc1_w = (const float*)d_in[17];
    const float* l2_fc1_b = (const float*)d_in[18];
    const float* l2_fc2_w = (const float*)d_in[19];
    const float* l2_fc2_b = (const float*)d_in[20];
    const float* l2_fc3_w = (const float*)d_in[21];
    const float* l2_fc3_b = (const float*)d_in[22];
    const float* attn_w1  = (const float*)d_in[23];
    const float* attn_b1  = (const float*)d_in[24];
    const float* attn_w2  = (const float*)d_in[25];
    const float* pred_w   = (const float*)d_in[26];
    const float* pred_b   = (const float*)d_in[27];
    float* out = (float*)d_out;

    cudaFuncSetAttribute(gemm_tc, cudaFuncAttributeMaxDynamicSharedMemorySize, GEMM_SMEM_BYTES);

    float *feat0, *feat1, *z, *tbuf, *s, *beta;
    __nv_bfloat16 *xh, *xl, *f0h, *f0l, *f1h, *f1l, *msgh, *msgl, *Hh, *Hl, *zh, *zl, *wth, *wtl;
    int *cnt, *rowptr, *cursor, *sorted;
    cudaGetSymbolAddress((void**)&feat0, g_feat0);
    cudaGetSymbolAddress((void**)&feat1, g_feat1);
    cudaGetSymbolAddress((void**)&z, g_z);
    cudaGetSymbolAddress((void**)&tbuf, g_t);
    cudaGetSymbolAddress((void**)&s, g_s);
    cudaGetSymbolAddress((void**)&beta, g_beta);
    cudaGetSymbolAddress((void**)&xh, g_xh);
    cudaGetSymbolAddress((void**)&xl, g_xl);
    cudaGetSymbolAddress((void**)&f0h, g_f0h);
    cudaGetSymbolAddress((void**)&f0l, g_f0l);
    cudaGetSymbolAddress((void**)&f1h, g_f1h);
    cudaGetSymbolAddress((void**)&f1l, g_f1l);
    cudaGetSymbolAddress((void**)&msgh, g_msgh);
    cudaGetSymbolAddress((void**)&msgl, g_msgl);
    cudaGetSymbolAddress((void**)&Hh, g_Hh);
    cudaGetSymbolAddress((void**)&Hl, g_Hl);
    cudaGetSymbolAddress((void**)&zh, g_zh);
    cudaGetSymbolAddress((void**)&zl, g_zl);
    cudaGetSymbolAddress((void**)&wth, g_wth);
    cudaGetSymbolAddress((void**)&wtl, g_wtl);
    cudaGetSymbolAddress((void**)&cnt, g_cnt);
    cudaGetSymbolAddress((void**)&rowptr, g_rowptr);
    cudaGetSymbolAddress((void**)&cursor, g_cursor);
    cudaGetSymbolAddress((void**)&sorted, g_sorted);

    // ---- weight + input conversions ----
    wconv_k<<<(16384 + 255) / 256, 256>>>(embed_w,  wth + OFF_EMBED, wtl + OFF_EMBED, 128, 1);
    wconv_k<<<(16384 + 255) / 256, 256>>>(attn_w1,  wth + OFF_ATTN,  wtl + OFF_ATTN,  128, 1);
    wconv_k<<<(98304 + 255) / 256, 256>>>(l1_fc1_w, wth + OFF_L1FC1, wtl + OFF_L1FC1, 256, 3);
    wconv_k<<<(294912 + 255) / 256, 256>>>(l1_fc2_w, wth + OFF_L1FC2, wtl + OFF_L1FC2, 768, 3);
    wconv_k<<<(98304 + 255) / 256, 256>>>(l1_fc3_w, wth + OFF_L1FC3, wtl + OFF_L1FC3, 256, 3);
    wconv_k<<<(98304 + 255) / 256, 256>>>(l2_fc1_w, wth + OFF_L2FC1, wtl + OFF_L2FC1, 256, 3);
    wconv_k<<<(294912 + 255) / 256, 256>>>(l2_fc2_w, wth + OFF_L2FC2, wtl + OFF_L2FC2, 768, 3);
    wconv_k<<<(98304 + 255) / 256, 256>>>(l2_fc3_w, wth + OFF_L2FC3, wtl + OFF_L2FC3, 256, 3);
    split_k<<<(CN0 * 128 + 255) / 256, 256>>>(x_user, xh, xl, (long)CN0 * 128);

    // feat0 = [x_user@embed_w + b | tss | rs]
    launch_gemm(xh, xl, wth + OFF_EMBED, wtl + OFF_EMBED, embed_b,
                feat0, nullptr, nullptr, CFEAT, CN0, 128, 0);
    fill_embed_k<<<CN0, 128>>>(tss, rs, src_nid0, feat0);
    split_k<<<((long)CN1 * CFEAT + 255) / 256, 256>>>(feat0, f0h, f0l, (long)CN1 * CFEAT);

    // ---- layer 1 ----
    for (int r = 0; r < CR; r++) {
        const int* es = e0_src + r * CE0;
        const int* ed = e0_dst + r * CE0;
        zeroi_k<<<(CN1 + 255) / 256, 256>>>(cnt, CN1);
        hist_k<<<(CE0 + 255) / 256, 256>>>(ed, CE0, cnt);
        scan_k<<<1, 1024>>>(cnt, rowptr, cursor, CN1);
        scatter_k<<<(CE0 + 255) / 256, 256>>>(es, ed, CE0, cursor, sorted);
        aggregate_k<<<CN1, 256>>>(feat0, rowptr, sorted, msgh, msgl);
        launch_gemm(msgh, msgl, wth + OFF_L1FC2 + (size_t)r * 768 * 128,
                    wtl + OFF_L1FC2 + (size_t)r * 768 * 128, l1_fc2_b + r * 128,
                    nullptr, Hh, Hl, 256, CN1, 768, 1);
        launch_gemm(f0h, f0l, wth + OFF_L1FC1 + (size_t)r * 256 * 128,
                    wtl + OFF_L1FC1 + (size_t)r * 256 * 128, l1_fc1_b + r * 128,
                    nullptr, Hh + 128, Hl + 128, 256, CN1, 256, 1);
        launch_gemm(Hh, Hl, wth + OFF_L1FC3 + (size_t)r * 256 * 128,
                    wtl + OFF_L1FC3 + (size_t)r * 256 * 128, l1_fc3_b + r * 128,
                    z + (size_t)r * CN1 * 128, zh + (size_t)r * CN1 * 128,
                    zl + (size_t)r * CN1 * 128, 128, CN1, 256, 0);
    }

    // ---- attention 1 -> feat1 ----
    zerof_k<<<1, 32>>>(s, CR);
    for (int r = 0; r < CR; r++) {
        launch_gemm(zh + (size_t)r * CN1 * 128, zl + (size_t)r * CN1 * 128,
                    wth + OFF_ATTN, wtl + OFF_ATTN, attn_b1,
                    tbuf, nullptr, nullptr, 128, CN1, 128, 0);
        attn_reduce_k<<<(CN1 + 7) / 8, 256>>>(tbuf, attn_w2, s + r, CN1);
    }
    beta_k<<<1, 32>>>(s, beta, 1.0f / (float)CN1);
    combine1_k<<<CN1, 256>>>(z, beta, tss, rs, src_nid1, feat1, f1h, f1l, CN1);

    // ---- layer 2 ----
    for (int r = 0; r < CR; r++) {
        const int* es = e1_src + r * CE1;
        const int* ed = e1_dst + r * CE1;
        zeroi_k<<<(CN2 + 255) / 256, 256>>>(cnt, CN2);
        hist_k<<<(CE1 + 255) / 256, 256>>>(ed, CE1, cnt);
        scan_k<<<1, 1024>>>(cnt, rowptr, cursor, CN2);
        scatter_k<<<(CE1 + 255) / 256, 256>>>(es, ed, CE1, cursor, sorted);
        aggregate_k<<<CN2, 256>>>(feat1, rowptr, sorted, msgh, msgl);
        launch_gemm(msgh, msgl, wth + OFF_L2FC2 + (size_t)r * 768 * 128,
                    wtl + OFF_L2FC2 + (size_t)r * 768 * 128, l2_fc2_b + r * 128,
                    nullptr, Hh, Hl, 256, CN2, 768, 1);
        launch_gemm(f1h, f1l, wth + OFF_L2FC1 + (size_t)r * 256 * 128,
                    wtl + OFF_L2FC1 + (size_t)r * 256 * 128, l2_fc1_b + r * 128,
                    nullptr, Hh + 128, Hl + 128, 256, CN2, 256, 1);
        launch_gemm(Hh, Hl, wth + OFF_L2FC3 + (size_t)r * 256 * 128,
                    wtl + OFF_L2FC3 + (size_t)r * 256 * 128, l2_fc3_b + r * 128,
                    z + (size_t)r * CN2 * 128, zh + (size_t)r * CN2 * 128,
                    zl + (size_t)r * CN2 * 128, 128, CN2, 256, 0);
    }

    // ---- attention 2 + prediction ----
    zerof_k<<<1, 32>>>(s, CR);
    for (int r = 0; r < CR; r++) {
        launch_gemm(zh + (size_t)r * CN2 * 128, zl + (size_t)r * CN2 * 128,
                    wth + OFF_ATTN, wtl + OFF_ATTN, attn_b1,
                    tbuf, nullptr, nullptr, 128, CN2, 128, 0);
        attn_reduce_k<<<(CN2 + 7) / 8, 256>>>(tbuf, attn_w2, s + r, CN2);
    }
    beta_k<<<1, 32>>>(s, beta, 1.0f / (float)CN2);
    final_k<<<(CN2 + 7) / 8, 256>>>(z, beta, pred_w, pred_b, out, CN2);
}

// round 5
// speedup vs baseline: 2.8702x; 1.5797x over previous
#include <cuda_runtime.h>
#include <cuda_bf16.h>
#include <math.h>
#include <stdint.h>

// ---------------- problem constants ----------------
#define CN0 100000
#define CN1 20000
#define CN2 4000
#define CR 3
#define CE0 160000
#define CE1 64000
#define CHID 128
#define CFEAT 256

// weight-transpose buffer offsets (elements)
#define OFF_EMBED 0
#define OFF_ATTN  16384
#define OFF_L1FC1 32768
#define OFF_L1FC2 131072
#define OFF_L1FC3 425984
#define OFF_L2FC1 524288
#define OFF_L2FC2 622592
#define OFF_L2FC3 917504
#define WT_TOTAL  1015808

// ---------------- device scratch ----------------
__device__ __align__(16) float g_feat0[CN0 * CFEAT];
__device__ __align__(16) float g_feat1[CN1 * CFEAT];
__device__ __align__(16) float g_z[CR * CN1 * CHID];
__device__ __align__(16) float g_t[CR * CN1 * CHID];
__device__ __align__(16) __nv_bfloat16 g_xh[CN0 * 128];
__device__ __align__(16) __nv_bfloat16 g_xl[CN0 * 128];
__device__ __align__(16) __nv_bfloat16 g_f0h[CN1 * CFEAT];
__device__ __align__(16) __nv_bfloat16 g_f0l[CN1 * CFEAT];
__device__ __align__(16) __nv_bfloat16 g_f1h[CN1 * CFEAT];
__device__ __align__(16) __nv_bfloat16 g_f1l[CN1 * CFEAT];
__device__ __align__(16) __nv_bfloat16 g_msgh[CR * CN1 * 768];
__device__ __align__(16) __nv_bfloat16 g_msgl[CR * CN1 * 768];
__device__ __align__(16) __nv_bfloat16 g_Hh[CR * CN1 * 256];
__device__ __align__(16) __nv_bfloat16 g_Hl[CR * CN1 * 256];
__device__ __align__(16) __nv_bfloat16 g_zh[CR * CN1 * CHID];
__device__ __align__(16) __nv_bfloat16 g_zl[CR * CN1 * CHID];
__device__ __align__(16) __nv_bfloat16 g_wth[WT_TOTAL];
__device__ __align__(16) __nv_bfloat16 g_wtl[WT_TOTAL];
__device__ int   g_cnt[CR * CN1];
__device__ int   g_rowptr[CR * (CN1 + 1)];
__device__ int   g_cursor[CR * (CN1 + 1)];
__device__ int   g_sorted[CR * CE0];
__device__ float g_s[CR];
__device__ float g_beta[CR];

// ---------------- helpers ----------------
__device__ __forceinline__ uint32_t smem_u32(const void* p) {
    uint32_t a;
    asm("{ .reg .u64 t; cvta.to.shared.u64 t, %1; cvt.u32.u64 %0, t; }" : "=r"(a) : "l"(p));
    return a;
}
__device__ __forceinline__ void bsplit(float v, __nv_bfloat16& h, __nv_bfloat16& l) {
    h = __float2bfloat16(v);
    l = __float2bfloat16(v - __bfloat162float(h));
}
__device__ __forceinline__ void cp16(uint32_t dst, const void* src, int valid) {
    asm volatile("cp.async.cg.shared.global [%0], [%1], 16, %2;"
                 :: "r"(dst), "l"(src), "r"(valid ? 16 : 0) : "memory");
}
template <int N> __device__ __forceinline__ void cpwait() {
    asm volatile("cp.async.wait_group %0;" :: "n"(N) : "memory");
}
__device__ __forceinline__ void cpcommit() {
    asm volatile("cp.async.commit_group;" ::: "memory");
}
__device__ __forceinline__ void mma16816(float* c, const uint32_t* a, uint32_t b0, uint32_t b1) {
    asm volatile("mma.sync.aligned.m16n8k16.row.col.f32.bf16.bf16.f32 "
        "{%0,%1,%2,%3}, {%4,%5,%6,%7}, {%8,%9}, {%0,%1,%2,%3};"
        : "+f"(c[0]), "+f"(c[1]), "+f"(c[2]), "+f"(c[3])
        : "r"(a[0]), "r"(a[1]), "r"(a[2]), "r"(a[3]), "r"(b0), "r"(b1));
}
__device__ __forceinline__ void ldmx4(uint32_t* r, uint32_t addr) {
    asm volatile("ldmatrix.sync.aligned.m8n8.x4.shared.b16 {%0,%1,%2,%3}, [%4];"
        : "=r"(r[0]), "=r"(r[1]), "=r"(r[2]), "=r"(r[3]) : "r"(addr));
}

// ---------------- tensor-core GEMM (mma.sync + ldmatrix, bf16 3-term split) ----------------
// grid.y = relation; per-relation strides for A/B/bias/C.
// C[M,128] = (Ah+Al)[M,K] @ (Bth+Btl)^T + bias ; Bt is [128,K] pre-transposed.
#define KC 32
#define SROW 40                       // padded smem row stride (elements)
#define MAT_BYTES (128 * SROW * 2)    // 10240
#define STAGE_BYTES (4 * MAT_BYTES)   // 40960
#define GEMM_SMEM_BYTES (2 * STAGE_BYTES)  // 81920

__global__ void __launch_bounds__(256)
gemm_tc(const __nv_bfloat16* __restrict__ Ah, const __nv_bfloat16* __restrict__ Al,
        const __nv_bfloat16* __restrict__ Bth, const __nv_bfloat16* __restrict__ Btl,
        const float* __restrict__ bias,
        float* __restrict__ Cf, __nv_bfloat16* __restrict__ Ch, __nv_bfloat16* __restrict__ Cl,
        int ldc, int M, int K, int relu,
        long aS, long bS, long biasS, long cS) {
    extern __shared__ __align__(16) char sm[];
    __shared__ float bias_s[128];
    uint32_t sb = smem_u32(sm);
    int t = threadIdx.x;
    int lane = t & 31, wid = t >> 5;
    int m0 = blockIdx.x * 128;
    int rrel = blockIdx.y;
    Ah += (size_t)rrel * aS;  Al += (size_t)rrel * aS;
    Bth += (size_t)rrel * bS; Btl += (size_t)rrel * bS;
    bias += (size_t)rrel * biasS;
    if (Cf) Cf += (size_t)rrel * cS;
    if (Ch) { Ch += (size_t)rrel * cS; Cl += (size_t)rrel * cS; }
    if (t < 128) bias_s[t] = bias[t];

    float acc[2][8][4];
#pragma unroll
    for (int i = 0; i < 2; i++)
#pragma unroll
        for (int j = 0; j < 8; j++)
#pragma unroll
            for (int q = 0; q < 4; q++) acc[i][j][q] = 0.f;

    const int nC = K >> 5;
    const int wm = (wid >> 1) * 32, wn = (wid & 1) * 64;
    const int t4 = lane >> 2, q2 = (lane & 3) * 2;
    const int g = lane >> 3, lr = lane & 7;

    auto load_stage = [&](int st, int c) {
        uint32_t base = sb + st * STAGE_BYTES;
        int kb = c * KC;
#pragma unroll
        for (int h = 0; h < 2; h++) {
            int chunk = t + h * 256;          // 0..511
            int row = chunk >> 2, seg = chunk & 3;
            uint32_t off = (uint32_t)(row * (SROW * 2) + seg * 16);
            int gk = kb + seg * 8;
            int av = (m0 + row) < M;
            size_t arow = (size_t)(av ? (m0 + row) : 0) * K + gk;
            cp16(base + off,                 Ah + arow, av);
            cp16(base + MAT_BYTES + off,     Al + arow, av);
            size_t brow = (size_t)row * K + gk;
            cp16(base + 2 * MAT_BYTES + off, Bth + brow, 1);
            cp16(base + 3 * MAT_BYTES + off, Btl + brow, 1);
        }
        cpcommit();
    };

    auto compute_stage = [&](int st) {
        uint32_t base = sb + st * STAGE_BYTES;
#pragma unroll
        for (int k16 = 0; k16 < 2; k16++) {
            int k0 = k16 * 16;
            // A fragments via ldmatrix: m0=(r0-7,k0) m1=(r8-15,k0) m2=(r0-7,k8) m3=(r8-15,k8)
            int arow = wm + (g & 1) * 8 + lr;
            int acol = k0 + (g >> 1) * 8;
            uint32_t ah[2][4], al[2][4];
#pragma unroll
            for (int i = 0; i < 2; i++) {
                uint32_t aoff = (uint32_t)(((arow + i * 16) * SROW + acol) * 2);
                ldmx4(ah[i], base + aoff);
                ldmx4(al[i], base + MAT_BYTES + aoff);
            }
            // B fragments: per jp, m0=(j n-rows,k0) m1=(j,k8) m2=(j+1,k0) m3=(j+1,k8)
            int bcol = k0 + (g & 1) * 8;
#pragma unroll
            for (int jp = 0; jp < 4; jp++) {
                int brow = wn + jp * 16 + (g >> 1) * 8 + lr;
                uint32_t boff = (uint32_t)((brow * SROW + bcol) * 2);
                uint32_t bh[4], bl[4];
                ldmx4(bh, base + 2 * MAT_BYTES + boff);
                ldmx4(bl, base + 3 * MAT_BYTES + boff);
#pragma unroll
                for (int jj = 0; jj < 2; jj++) {
                    int j = jp * 2 + jj;
#pragma unroll
                    for (int i = 0; i < 2; i++) {
                        mma16816(acc[i][j], ah[i], bh[jj * 2], bh[jj * 2 + 1]);
                        mma16816(acc[i][j], ah[i], bl[jj * 2], bl[jj * 2 + 1]);
                        mma16816(acc[i][j], al[i], bh[jj * 2], bh[jj * 2 + 1]);
                    }
                }
            }
        }
    };

    load_stage(0, 0);
    for (int c = 0; c < nC; c++) {
        if (c + 1 < nC) {
            load_stage((c + 1) & 1, c + 1);
            cpwait<1>();
        } else {
            cpwait<0>();
        }
        __syncthreads();
        compute_stage(c & 1);
        __syncthreads();
    }

    // epilogue: bias + relu, write fp32 and/or bf16 split
#pragma unroll
    for (int i = 0; i < 2; i++) {
        int r0 = m0 + wm + i * 16 + t4;
#pragma unroll
        for (int j = 0; j < 8; j++) {
            int col = wn + j * 8 + q2;
            float b0v = bias_s[col], b1v = bias_s[col + 1];
            float v00 = acc[i][j][0] + b0v, v01 = acc[i][j][1] + b1v;
            float v10 = acc[i][j][2] + b0v, v11 = acc[i][j][3] + b1v;
            if (relu) {
                v00 = fmaxf(v00, 0.f); v01 = fmaxf(v01, 0.f);
                v10 = fmaxf(v10, 0.f); v11 = fmaxf(v11, 0.f);
            }
            if (r0 < M) {
                if (Cf) *(float2*)(Cf + (size_t)r0 * ldc + col) = make_float2(v00, v01);
                if (Ch) {
                    __nv_bfloat16 h0, l0, h1, l1;
                    bsplit(v00, h0, l0); bsplit(v01, h1, l1);
                    __nv_bfloat162 hh; hh.x = h0; hh.y = h1;
                    __nv_bfloat162 ll; ll.x = l0; ll.y = l1;
                    *(__nv_bfloat162*)(Ch + (size_t)r0 * ldc + col) = hh;
                    *(__nv_bfloat162*)(Cl + (size_t)r0 * ldc + col) = ll;
                }
            }
            if (r0 + 8 < M) {
                if (Cf) *(float2*)(Cf + (size_t)(r0 + 8) * ldc + col) = make_float2(v10, v11);
                if (Ch) {
                    __nv_bfloat16 h0, l0, h1, l1;
                    bsplit(v10, h0, l0); bsplit(v11, h1, l1);
                    __nv_bfloat162 hh; hh.x = h0; hh.y = h1;
                    __nv_bfloat162 ll; ll.x = l0; ll.y = l1;
                    *(__nv_bfloat162*)(Ch + (size_t)(r0 + 8) * ldc + col) = hh;
                    *(__nv_bfloat162*)(Cl + (size_t)(r0 + 8) * ldc + col) = ll;
                }
            }
        }
    }
}

// ---------------- conversions ----------------
__global__ void split_k(const float* __restrict__ src, __nv_bfloat16* __restrict__ h,
                        __nv_bfloat16* __restrict__ l, long n) {
    long i = (long)blockIdx.x * blockDim.x + threadIdx.x;
    if (i < n) {
        __nv_bfloat16 hh, ll;
        bsplit(src[i], hh, ll);
        h[i] = hh; l[i] = ll;
    }
}
// w: [R,K,128] -> th/tl: [R,128,K]
__global__ void wconv_k(const float* __restrict__ w, __nv_bfloat16* __restrict__ th,
                        __nv_bfloat16* __restrict__ tl, int K, int R) {
    long i = (long)blockIdx.x * blockDim.x + threadIdx.x;
    long tot = (long)R * K * 128;
    if (i >= tot) return;
    int r = (int)(i / ((long)K * 128));
    int rem = (int)(i % ((long)K * 128));
    int k = rem >> 7, n = rem & 127;
    __nv_bfloat16 hh, ll;
    bsplit(w[i], hh, ll);
    size_t o = (size_t)r * K * 128 + (size_t)n * K + k;
    th[o] = hh; tl[o] = ll;
}

// ---------------- CSR build (batched over R) ----------------
__global__ void zeroi_k(int* p, int n) {
    int i = blockIdx.x * blockDim.x + threadIdx.x;
    if (i < n) p[i] = 0;
}
__global__ void zerof_k(float* p, int n) {
    int i = blockIdx.x * blockDim.x + threadIdx.x;
    if (i < n) p[i] = 0.f;
}
// dst: [R][E] contiguous; cnt: [R][n]
__global__ void hist_k(const int* __restrict__ dst, int E, int n, int* cnt) {
    int e = blockIdx.x * blockDim.x + threadIdx.x;
    if (e < CR * E) {
        int r = e / E;
        atomicAdd(&cnt[r * n + dst[e]], 1);
    }
}
// grid.x = R; per-relation exclusive scan
__global__ void scan_k(const int* __restrict__ cnt_g, int* rowptr_g, int* cursor_g, int n) {
    int rel = blockIdx.x;
    const int* cnt = cnt_g + rel * n;
    int* rowptr = rowptr_g + rel * (n + 1);
    int* cursor = cursor_g + rel * (n + 1);
    __shared__ int sh[1024];
    __shared__ int carry_s;
    if (threadIdx.x == 0) carry_s = 0;
    __syncthreads();
    for (int base = 0; base < n; base += 1024) {
        int i = base + threadIdx.x;
        int v = (i < n) ? cnt[i] : 0;
        sh[threadIdx.x] = v;
        __syncthreads();
        for (int off = 1; off < 1024; off <<= 1) {
            int add = (threadIdx.x >= off) ? sh[threadIdx.x - off] : 0;
            __syncthreads();
            sh[threadIdx.x] += add;
            __syncthreads();
        }
        int carry = carry_s;
        if (i < n) {
            int excl = carry + sh[threadIdx.x] - v;
            rowptr[i] = excl;
            cursor[i] = excl;
        }
        __syncthreads();
        if (threadIdx.x == 0) carry_s = carry + sh[1023];
        __syncthreads();
    }
    if (threadIdx.x == 0) rowptr[n] = carry_s;
}
__global__ void scatter_k(const int* __restrict__ src, const int* __restrict__ dst,
                          int E, int n, int* cursor, int* sorted) {
    int e = blockIdx.x * blockDim.x + threadIdx.x;
    if (e < CR * E) {
        int r = e / E;
        int p = atomicAdd(&cursor[r * (n + 1) + dst[e]], 1);
        sorted[r * E + p] = src[e];
    }
}

// ---------------- segment aggregation (batched over R) -> bf16 split msg ----------------
__global__ void aggregate_k(const float* __restrict__ feat,
                            const int* __restrict__ rowptr_g,
                            const int* __restrict__ sorted_g,
                            __nv_bfloat16* __restrict__ mh_g,
                            __nv_bfloat16* __restrict__ ml_g,
                            int N, int E) {
    int rel = blockIdx.y;
    const int* rowptr = rowptr_g + rel * (N + 1);
    const int* sorted = sorted_g + rel * E;
    __nv_bfloat16* mh = mh_g + (size_t)rel * N * 768;
    __nv_bfloat16* ml = ml_g + (size_t)rel * N * 768;
    int n = blockIdx.x;
    int start = rowptr[n], end = rowptr[n + 1];
    int deg = end - start;
    int f = threadIdx.x;
    float sum = 0.f, mx = -3.402823e38f;
    __shared__ int eids[256];
    for (int base = start; base < end; base += 256) {
        int cnt = min(256, end - base);
        __syncthreads();
        if (threadIdx.x < cnt) eids[threadIdx.x] = sorted[base + threadIdx.x];
        __syncthreads();
        for (int i = 0; i < cnt; i++) {
            float v = feat[(size_t)eids[i] * CFEAT + f];
            sum += v;
            mx = fmaxf(mx, v);
        }
    }
    if (deg == 0) mx = 0.f;
    float mean = sum / (float)max(deg, 1);
    size_t o = (size_t)n * 768 + f;
    __nv_bfloat16 h, l;
    bsplit(mx, h, l);   mh[o] = h;        ml[o] = l;
    bsplit(mean, h, l); mh[o + 256] = h;  ml[o + 256] = l;
    bsplit(sum, h, l);  mh[o + 512] = h;  ml[o + 512] = l;
}

// ---------------- feature assembly ----------------
__global__ void fill_embed_k(const float* __restrict__ tss, const float* __restrict__ rs,
                             const int* __restrict__ nid, float* __restrict__ feat) {
    int n = blockIdx.x;
    int c = threadIdx.x;
    int id = nid[n];
    float v = (c < 64) ? tss[(size_t)id * 64 + c] : rs[(size_t)id * 64 + (c - 64)];
    feat[(size_t)n * CFEAT + 128 + c] = v;
}
__global__ void combine1_k(const float* __restrict__ z, const float* __restrict__ beta,
                           const float* __restrict__ tss, const float* __restrict__ rs,
                           const int* __restrict__ nid, float* __restrict__ feat1,
                           __nv_bfloat16* __restrict__ f1h, __nv_bfloat16* __restrict__ f1l,
                           int N) {
    int n = blockIdx.x;
    int c = threadIdx.x;  // 0..255
    float v;
    if (c < 128) {
        v = beta[0] * z[(size_t)n * 128 + c]
          + beta[1] * z[(size_t)N * 128 + (size_t)n * 128 + c]
          + beta[2] * z[2 * (size_t)N * 128 + (size_t)n * 128 + c];
        v = fmaxf(v, 0.f);
    } else if (c < 192) {
        v = tss[(size_t)nid[n] * 64 + (c - 128)];
    } else {
        v = rs[(size_t)nid[n] * 64 + (c - 192)];
    }
    size_t o = (size_t)n * CFEAT + c;
    feat1[o] = v;
    __nv_bfloat16 h, l;
    bsplit(v, h, l);
    f1h[o] = h; f1l[o] = l;
}

// ---------------- semantic attention (batched over R) ----------------
__global__ void attn_reduce_k(const float* __restrict__ t_g, const float* __restrict__ w2,
                              float* s_g, int N) {
    int rel = blockIdx.y;
    const float* t = t_g + (size_t)rel * N * 128;
    int n = blockIdx.x * 8 + (threadIdx.x >> 5);
    int lane = threadIdx.x & 31;
    float part = 0.f;
    if (n < N) {
#pragma unroll
        for (int j = 0; j < 4; j++) {
            int c = lane + 32 * j;
            part += tanhf(t[(size_t)n * 128 + c]) * w2[c];
        }
    }
    for (int o = 16; o; o >>= 1) part += __shfl_xor_sync(0xffffffffu, part, o);
    __shared__ float bs[8];
    if (lane == 0) bs[threadIdx.x >> 5] = part;
    __syncthreads();
    if (threadIdx.x == 0) {
        float tot = 0.f;
        for (int i = 0; i < 8; i++) tot += bs[i];
        atomicAdd(s_g + rel, tot);
    }
}
__global__ void beta_k(const float* __restrict__ s, float* beta, float invN) {
    if (threadIdx.x == 0) {
        float w0 = s[0] * invN, w1 = s[1] * invN, w2 = s[2] * invN;
        float m = fmaxf(w0, fmaxf(w1, w2));
        float e0 = expf(w0 - m), e1 = expf(w1 - m), e2 = expf(w2 - m);
        float d = e0 + e1 + e2;
        beta[0] = e0 / d; beta[1] = e1 / d; beta[2] = e2 / d;
    }
}
__global__ void final_k(const float* __restrict__ z, const float* __restrict__ beta,
                        const float* __restrict__ pred_w, const float* __restrict__ pred_b,
                        float* __restrict__ out, int N) {
    int n = blockIdx.x * 8 + (threadIdx.x >> 5);
    int lane = threadIdx.x & 31;
    if (n >= N) return;
    float acc = 0.f;
#pragma unroll
    for (int j = 0; j < 4; j++) {
        int c = lane + 32 * j;
        float h = beta[0] * z[(size_t)n * 128 + c]
                + beta[1] * z[(size_t)N * 128 + (size_t)n * 128 + c]
                + beta[2] * z[2 * (size_t)N * 128 + (size_t)n * 128 + c];
        acc += h * pred_w[c];
    }
    for (int o = 16; o; o >>= 1) acc += __shfl_xor_sync(0xffffffffu, acc, o);
    if (lane == 0) out[n] = 1.f / (1.f + expf(-(acc + pred_b[0])));
}

// ---------------- host orchestration ----------------
static inline void launch_gemm(int R, const __nv_bfloat16* Ah, const __nv_bfloat16* Al,
                               const __nv_bfloat16* Bth, const __nv_bfloat16* Btl,
                               const float* bias, float* Cf, __nv_bfloat16* Ch,
                               __nv_bfloat16* Cl, int ldc, int M, int K, int relu,
                               long aS, long bS, long biasS, long cS) {
    dim3 grid((M + 127) / 128, R);
    gemm_tc<<<grid, 256, GEMM_SMEM_BYTES>>>(Ah, Al, Bth, Btl, bias, Cf, Ch, Cl,
                                            ldc, M, K, relu, aS, bS, biasS, cS);
}

extern "C" void kernel_launch(void* const* d_in, const int* in_sizes, int n_in,
                              void* d_out, int out_size) {
    const float* x_user   = (const float*)d_in[0];
    const float* tss      = (const float*)d_in[1];
    const float* rs       = (const float*)d_in[2];
    const int*   src_nid0 = (const int*)d_in[3];
    const int*   src_nid1 = (const int*)d_in[4];
    const int*   e0_src   = (const int*)d_in[5];
    const int*   e0_dst   = (const int*)d_in[6];
    const int*   e1_src   = (const int*)d_in[7];
    const int*   e1_dst   = (const int*)d_in[8];
    const float* embed_w  = (const float*)d_in[9];
    const float* embed_b  = (const float*)d_in[10];
    const float* l1_fc1_w = (const float*)d_in[11];
    const float* l1_fc1_b = (const float*)d_in[12];
    const float* l1_fc2_w = (const float*)d_in[13];
    const float* l1_fc2_b = (const float*)d_in[14];
    const float* l1_fc3_w = (const float*)d_in[15];
    const float* l1_fc3_b = (const float*)d_in[16];
    const float* l2_fc1_w = (const float*)d_in[17];
    const float* l2_fc1_b = (const float*)d_in[18];
    const float* l2_fc2_w = (const float*)d_in[19];
    const float* l2_fc2_b = (const float*)d_in[20];
    const float* l2_fc3_w = (const float*)d_in[21];
    const float* l2_fc3_b = (const float*)d_in[22];
    const float* attn_w1  = (const float*)d_in[23];
    const float* attn_b1  = (const float*)d_in[24];
    const float* attn_w2  = (const float*)d_in[25];
    const float* pred_w   = (const float*)d_in[26];
    const float* pred_b   = (const float*)d_in[27];
    float* out = (float*)d_out;

    cudaFuncSetAttribute(gemm_tc, cudaFuncAttributeMaxDynamicSharedMemorySize, GEMM_SMEM_BYTES);

    float *feat0, *feat1, *z, *tbuf, *s, *beta;
    __nv_bfloat16 *xh, *xl, *f0h, *f0l, *f1h, *f1l, *msgh, *msgl, *Hh, *Hl, *zh, *zl, *wth, *wtl;
    int *cnt, *rowptr, *cursor, *sorted;
    cudaGetSymbolAddress((void**)&feat0, g_feat0);
    cudaGetSymbolAddress((void**)&feat1, g_feat1);
    cudaGetSymbolAddress((void**)&z, g_z);
    cudaGetSymbolAddress((void**)&tbuf, g_t);
    cudaGetSymbolAddress((void**)&s, g_s);
    cudaGetSymbolAddress((void**)&beta, g_beta);
    cudaGetSymbolAddress((void**)&xh, g_xh);
    cudaGetSymbolAddress((void**)&xl, g_xl);
    cudaGetSymbolAddress((void**)&f0h, g_f0h);
    cudaGetSymbolAddress((void**)&f0l, g_f0l);
    cudaGetSymbolAddress((void**)&f1h, g_f1h);
    cudaGetSymbolAddress((void**)&f1l, g_f1l);
    cudaGetSymbolAddress((void**)&msgh, g_msgh);
    cudaGetSymbolAddress((void**)&msgl, g_msgl);
    cudaGetSymbolAddress((void**)&Hh, g_Hh);
    cudaGetSymbolAddress((void**)&Hl, g_Hl);
    cudaGetSymbolAddress((void**)&zh, g_zh);
    cudaGetSymbolAddress((void**)&zl, g_zl);
    cudaGetSymbolAddress((void**)&wth, g_wth);
    cudaGetSymbolAddress((void**)&wtl, g_wtl);
    cudaGetSymbolAddress((void**)&cnt, g_cnt);
    cudaGetSymbolAddress((void**)&rowptr, g_rowptr);
    cudaGetSymbolAddress((void**)&cursor, g_cursor);
    cudaGetSymbolAddress((void**)&sorted, g_sorted);

    // ---- weight + input conversions ----
    wconv_k<<<(16384 + 255) / 256, 256>>>(embed_w,  wth + OFF_EMBED, wtl + OFF_EMBED, 128, 1);
    wconv_k<<<(16384 + 255) / 256, 256>>>(attn_w1,  wth + OFF_ATTN,  wtl + OFF_ATTN,  128, 1);
    wconv_k<<<(98304 + 255) / 256, 256>>>(l1_fc1_w, wth + OFF_L1FC1, wtl + OFF_L1FC1, 256, 3);
    wconv_k<<<(294912 + 255) / 256, 256>>>(l1_fc2_w, wth + OFF_L1FC2, wtl + OFF_L1FC2, 768, 3);
    wconv_k<<<(98304 + 255) / 256, 256>>>(l1_fc3_w, wth + OFF_L1FC3, wtl + OFF_L1FC3, 256, 3);
    wconv_k<<<(98304 + 255) / 256, 256>>>(l2_fc1_w, wth + OFF_L2FC1, wtl + OFF_L2FC1, 256, 3);
    wconv_k<<<(294912 + 255) / 256, 256>>>(l2_fc2_w, wth + OFF_L2FC2, wtl + OFF_L2FC2, 768, 3);
    wconv_k<<<(98304 + 255) / 256, 256>>>(l2_fc3_w, wth + OFF_L2FC3, wtl + OFF_L2FC3, 256, 3);
    split_k<<<(CN0 * 128 + 255) / 256, 256>>>(x_user, xh, xl, (long)CN0 * 128);

    // feat0 = [x_user@embed_w + b | tss | rs]
    launch_gemm(1, xh, xl, wth + OFF_EMBED, wtl + OFF_EMBED, embed_b,
                feat0, nullptr, nullptr, CFEAT, CN0, 128, 0, 0, 0, 0, 0);
    fill_embed_k<<<CN0, 128>>>(tss, rs, src_nid0, feat0);
    split_k<<<((long)CN1 * CFEAT + 255) / 256, 256>>>(feat0, f0h, f0l, (long)CN1 * CFEAT);

    // ---- layer 1 (all relations batched) ----
    zeroi_k<<<(CR * CN1 + 255) / 256, 256>>>(cnt, CR * CN1);
    hist_k<<<(CR * CE0 + 255) / 256, 256>>>(e0_dst, CE0, CN1, cnt);
    scan_k<<<CR, 1024>>>(cnt, rowptr, cursor, CN1);
    scatter_k<<<(CR * CE0 + 255) / 256, 256>>>(e0_src, e0_dst, CE0, CN1, cursor, sorted);
    aggregate_k<<<dim3(CN1, CR), 256>>>(feat0, rowptr, sorted, msgh, msgl, CN1, CE0);
    launch_gemm(CR, msgh, msgl, wth + OFF_L1FC2, wtl + OFF_L1FC2, l1_fc2_b,
                nullptr, Hh, Hl, 256, CN1, 768, 1,
                (long)CN1 * 768, 768L * 128, 128, (long)CN1 * 256);
    launch_gemm(CR, f0h, f0l, wth + OFF_L1FC1, wtl + OFF_L1FC1, l1_fc1_b,
                nullptr, Hh + 128, Hl + 128, 256, CN1, 256, 1,
                0, 256L * 128, 128, (long)CN1 * 256);
    launch_gemm(CR, Hh, Hl, wth + OFF_L1FC3, wtl + OFF_L1FC3, l1_fc3_b,
                z, zh, zl, 128, CN1, 256, 0,
                (long)CN1 * 256, 256L * 128, 128, (long)CN1 * 128);

    // ---- attention 1 -> feat1 ----
    zerof_k<<<1, 32>>>(s, CR);
    launch_gemm(CR, zh, zl, wth + OFF_ATTN, wtl + OFF_ATTN, attn_b1,
                tbuf, nullptr, nullptr, 128, CN1, 128, 0,
                (long)CN1 * 128, 0, 0, (long)CN1 * 128);
    attn_reduce_k<<<dim3((CN1 + 7) / 8, CR), 256>>>(tbuf, attn_w2, s, CN1);
    beta_k<<<1, 32>>>(s, beta, 1.0f / (float)CN1);
    combine1_k<<<CN1, 256>>>(z, beta, tss, rs, src_nid1, feat1, f1h, f1l, CN1);

    // ---- layer 2 (batched) ----
    zeroi_k<<<(CR * CN2 + 255) / 256, 256>>>(cnt, CR * CN2);
    hist_k<<<(CR * CE1 + 255) / 256, 256>>>(e1_dst, CE1, CN2, cnt);
    scan_k<<<CR, 1024>>>(cnt, rowptr, cursor, CN2);
    scatter_k<<<(CR * CE1 + 255) / 256, 256>>>(e1_src, e1_dst, CE1, CN2, cursor, sorted);
    aggregate_k<<<dim3(CN2, CR), 256>>>(feat1, rowptr, sorted, msgh, msgl, CN2, CE1);
    launch_gemm(CR, msgh, msgl, wth + OFF_L2FC2, wtl + OFF_L2FC2, l2_fc2_b,
                nullptr, Hh, Hl, 256, CN2, 768, 1,
                (long)CN2 * 768, 768L * 128, 128, (long)CN2 * 256);
    launch_gemm(CR, f1h, f1l, wth + OFF_L2FC1, wtl + OFF_L2FC1, l2_fc1_b,
                nullptr, Hh + 128, Hl + 128, 256, CN2, 256, 1,
                0, 256L * 128, 128, (long)CN2 * 256);
    launch_gemm(CR, Hh, Hl, wth + OFF_L2FC3, wtl + OFF_L2FC3, l2_fc3_b,
                z, zh, zl, 128, CN2, 256, 0,
                (long)CN2 * 256, 256L * 128, 128, (long)CN2 * 128);

    // ---- attention 2 + prediction ----
    zerof_k<<<1, 32>>>(s, CR);
    launch_gemm(CR, zh, zl, wth + OFF_ATTN, wtl + OFF_ATTN, attn_b1,
                tbuf, nullptr, nullptr, 128, CN2, 128, 0,
                (long)CN2 * 128, 0, 0, (long)CN2 * 128);
    attn_reduce_k<<<dim3((CN2 + 7) / 8, CR), 256>>>(tbuf, attn_w2, s, CN2);
    beta_k<<<1, 32>>>(s, beta, 1.0f / (float)CN2);
    final_k<<<(CN2 + 7) / 8, 256>>>(z, beta, pred_w, pred_b, out, CN2);
}